// round 3
// baseline (speedup 1.0000x reference)
#include <cuda_runtime.h>

#define NTOK 4096
#define HID  256
#define HEADS 8
#define HD   32
#define EPSV 1e-5f

// ---------------- scratch (no allocs allowed) ----------------
__device__ float g_Q[NTOK * HID];
__device__ float g_K[NTOK * HID];
__device__ float g_V[NTOK * HID];
__device__ float g_attn[NTOK * HID];
__device__ float g_y1[NTOK * HID];
__device__ float g_z[NTOK * 2 * HID];
__device__ float g_y2[NTOK * HID];
__device__ float g_a1[HID], g_b1[HID], g_a2[HID], g_b2[HID];

// ---------------- generic fused SGEMM ----------------
// C[M,Nout] = relu?( alpha*(X' @ W^T + bias) + res' )
//   X'   = ain ? X*ain[col]+bin[col] : X          (per K-column affine)
//   res' = res ? (ra ? res*ra[col]+rb[col] : res) : 0
// BM=BN=64, BK=16, 256 threads, 4x4 micro-tile.
__global__ __launch_bounds__(256) void gemm_fused(
    const float* __restrict__ X, const float* __restrict__ W,
    const float* __restrict__ bias, const float* __restrict__ res,
    const float* __restrict__ ain, const float* __restrict__ bin,
    const float* __restrict__ ra, const float* __restrict__ rb,
    float* __restrict__ C, int M, int K, int Nout, float alpha, int relu)
{
    __shared__ float Xs[16][64];
    __shared__ float Ws[16][64];

    const int tid = threadIdx.x;
    const int tx = tid & 15, ty = tid >> 4;
    const int n0 = blockIdx.x * 64, m0 = blockIdx.y * 64;
    const int lr = tid >> 2;          // 0..63 row within tile
    const int lk = (tid & 3) * 4;     // k offset 0,4,8,12

    float acc[4][4] = {};

    for (int kt = 0; kt < K; kt += 16) {
        float4 xv = *(const float4*)&X[(size_t)(m0 + lr) * K + kt + lk];
        if (ain) {
            int c = kt + lk;
            xv.x = xv.x * ain[c + 0] + bin[c + 0];
            xv.y = xv.y * ain[c + 1] + bin[c + 1];
            xv.z = xv.z * ain[c + 2] + bin[c + 2];
            xv.w = xv.w * ain[c + 3] + bin[c + 3];
        }
        float4 wv = *(const float4*)&W[(size_t)(n0 + lr) * K + kt + lk];
        Xs[lk + 0][lr] = xv.x; Xs[lk + 1][lr] = xv.y;
        Xs[lk + 2][lr] = xv.z; Xs[lk + 3][lr] = xv.w;
        Ws[lk + 0][lr] = wv.x; Ws[lk + 1][lr] = wv.y;
        Ws[lk + 2][lr] = wv.z; Ws[lk + 3][lr] = wv.w;
        __syncthreads();

        #pragma unroll
        for (int kk = 0; kk < 16; kk++) {
            float4 a = *(const float4*)&Xs[kk][ty * 4];
            float4 b = *(const float4*)&Ws[kk][tx * 4];
            acc[0][0] += a.x * b.x; acc[0][1] += a.x * b.y; acc[0][2] += a.x * b.z; acc[0][3] += a.x * b.w;
            acc[1][0] += a.y * b.x; acc[1][1] += a.y * b.y; acc[1][2] += a.y * b.z; acc[1][3] += a.y * b.w;
            acc[2][0] += a.z * b.x; acc[2][1] += a.z * b.y; acc[2][2] += a.z * b.z; acc[2][3] += a.z * b.w;
            acc[3][0] += a.w * b.x; acc[3][1] += a.w * b.y; acc[3][2] += a.w * b.z; acc[3][3] += a.w * b.w;
        }
        __syncthreads();
    }

    #pragma unroll
    for (int i = 0; i < 4; i++) {
        int row = m0 + ty * 4 + i;
        #pragma unroll
        for (int j = 0; j < 4; j++) {
            int col = n0 + tx * 4 + j;
            float v = (acc[i][j] + bias[col]) * alpha;
            if (res) {
                float r = res[(size_t)row * Nout + col];
                if (ra) r = r * ra[col] + rb[col];
                v += r;
            }
            if (relu) v = fmaxf(v, 0.f);
            C[(size_t)row * Nout + col] = v;
        }
    }
}

// ---------------- flash attention with multiplicative A mask ----------------
// grid: (NTOK/64, HEADS); block: 256 threads (16x16), 4x4 score micro-tile.
// Q/K/V layouts: flat [HEADS][NTOK][32] (== raw reshape of [NTOK,256]).
__global__ __launch_bounds__(256) void flash_attn(
    const float* __restrict__ Q, const float* __restrict__ Kb,
    const float* __restrict__ Vb, const float* __restrict__ A,
    float* __restrict__ O)
{
    __shared__ float q_s[64][33];
    __shared__ float k_s[64][33];
    __shared__ float v_s[64][33];
    __shared__ float p_s[64][65];

    const int tid = threadIdx.x;
    const int tx = tid & 15, ty = tid >> 4;
    const int h  = blockIdx.y;
    const int q0 = blockIdx.x * 64;
    const float* __restrict__ Qh = Q  + (size_t)h * NTOK * HD;
    const float* __restrict__ Kh = Kb + (size_t)h * NTOK * HD;
    const float* __restrict__ Vh = Vb + (size_t)h * NTOK * HD;

    // load Q tile (64x32) once
    #pragma unroll
    for (int i = 0; i < 2; i++) {
        int v4 = tid + i * 256;             // vec4 index 0..511
        int r = v4 >> 3, d = (v4 & 7) * 4;
        float4 qv = *(const float4*)&Qh[(size_t)(q0 + r) * HD + d];
        q_s[r][d + 0] = qv.x; q_s[r][d + 1] = qv.y;
        q_s[r][d + 2] = qv.z; q_s[r][d + 3] = qv.w;
    }

    float m[4], l[4], o0[4], o1[4];
    #pragma unroll
    for (int i = 0; i < 4; i++) { m[i] = -1e30f; l[i] = 0.f; o0[i] = 0.f; o1[i] = 0.f; }

    const int dd = tx * 2;   // the 2 output dims this thread owns

    for (int kt = 0; kt < NTOK / 64; kt++) {
        const int k0 = kt * 64;
        __syncthreads();   // prior PV done; safe to refill k/v and later p
        #pragma unroll
        for (int i = 0; i < 2; i++) {
            int v4 = tid + i * 256;
            int r = v4 >> 3, d = (v4 & 7) * 4;
            float4 kv = *(const float4*)&Kh[(size_t)(k0 + r) * HD + d];
            float4 vv = *(const float4*)&Vh[(size_t)(k0 + r) * HD + d];
            k_s[r][d + 0] = kv.x; k_s[r][d + 1] = kv.y;
            k_s[r][d + 2] = kv.z; k_s[r][d + 3] = kv.w;
            v_s[r][d + 0] = vv.x; v_s[r][d + 1] = vv.y;
            v_s[r][d + 2] = vv.z; v_s[r][d + 3] = vv.w;
        }
        // prefetch A tile into registers (latency hidden under dot phase)
        float4 a4[4];
        #pragma unroll
        for (int i = 0; i < 4; i++)
            a4[i] = *(const float4*)&A[(size_t)(q0 + ty * 4 + i) * NTOK + k0 + tx * 4];
        __syncthreads();

        // scores: 4x4 dot products over d=32
        float s[4][4] = {};
        #pragma unroll
        for (int d = 0; d < HD; d++) {
            float aq0 = q_s[ty * 4 + 0][d], aq1 = q_s[ty * 4 + 1][d];
            float aq2 = q_s[ty * 4 + 2][d], aq3 = q_s[ty * 4 + 3][d];
            float bk0 = k_s[tx * 4 + 0][d], bk1 = k_s[tx * 4 + 1][d];
            float bk2 = k_s[tx * 4 + 2][d], bk3 = k_s[tx * 4 + 3][d];
            s[0][0] += aq0 * bk0; s[0][1] += aq0 * bk1; s[0][2] += aq0 * bk2; s[0][3] += aq0 * bk3;
            s[1][0] += aq1 * bk0; s[1][1] += aq1 * bk1; s[1][2] += aq1 * bk2; s[1][3] += aq1 * bk3;
            s[2][0] += aq2 * bk0; s[2][1] += aq2 * bk1; s[2][2] += aq2 * bk2; s[2][3] += aq2 * bk3;
            s[3][0] += aq3 * bk0; s[3][1] += aq3 * bk1; s[3][2] += aq3 * bk2; s[3][3] += aq3 * bk3;
        }
        // multiplicative adjacency mask
        #pragma unroll
        for (int i = 0; i < 4; i++) {
            s[i][0] *= a4[i].x; s[i][1] *= a4[i].y; s[i][2] *= a4[i].z; s[i][3] *= a4[i].w;
        }
        // online softmax per row (row owned by the 16 tx-threads; state replicated)
        #pragma unroll
        for (int i = 0; i < 4; i++) {
            float mt = fmaxf(fmaxf(s[i][0], s[i][1]), fmaxf(s[i][2], s[i][3]));
            #pragma unroll
            for (int off = 8; off; off >>= 1)
                mt = fmaxf(mt, __shfl_xor_sync(0xffffffffu, mt, off));
            float mnew = fmaxf(m[i], mt);
            float corr = __expf(m[i] - mnew);
            l[i] *= corr; o0[i] *= corr; o1[i] *= corr;
            m[i] = mnew;
            float p0 = __expf(s[i][0] - mnew);
            float p1 = __expf(s[i][1] - mnew);
            float p2 = __expf(s[i][2] - mnew);
            float p3 = __expf(s[i][3] - mnew);
            float rs = p0 + p1 + p2 + p3;
            #pragma unroll
            for (int off = 8; off; off >>= 1)
                rs += __shfl_xor_sync(0xffffffffu, rs, off);
            l[i] += rs;
            p_s[ty * 4 + i][tx * 4 + 0] = p0;
            p_s[ty * 4 + i][tx * 4 + 1] = p1;
            p_s[ty * 4 + i][tx * 4 + 2] = p2;
            p_s[ty * 4 + i][tx * 4 + 3] = p3;
        }
        __syncthreads();

        // PV accumulate: o[i][dd..dd+1] += sum_kj p[i][kj] * v[kj][dd..dd+1]
        #pragma unroll 8
        for (int kj = 0; kj < 64; kj++) {
            float v0 = v_s[kj][dd], v1 = v_s[kj][dd + 1];
            #pragma unroll
            for (int i = 0; i < 4; i++) {
                float pp = p_s[ty * 4 + i][kj];
                o0[i] += pp * v0;
                o1[i] += pp * v1;
            }
        }
    }

    #pragma unroll
    for (int i = 0; i < 4; i++) {
        float inv = 1.f / l[i];
        size_t base = (size_t)h * NTOK * HD + (size_t)(q0 + ty * 4 + i) * HD + dd;
        O[base]     = o0[i] * inv;
        O[base + 1] = o1[i] * inv;
    }
}

// ---------------- batchnorm column stats -> fused scale/shift ----------------
__global__ __launch_bounds__(128) void colstats(
    const float* __restrict__ Y, const float* __restrict__ g,
    const float* __restrict__ be, float* __restrict__ a, float* __restrict__ b)
{
    const int c = blockIdx.x;
    const int t = threadIdx.x;
    float s = 0.f, sq = 0.f;
    for (int r = t; r < NTOK; r += 128) {
        float v = Y[(size_t)r * HID + c];
        s += v; sq += v * v;
    }
    __shared__ float ss[128], qq[128];
    ss[t] = s; qq[t] = sq;
    __syncthreads();
    for (int off = 64; off; off >>= 1) {
        if (t < off) { ss[t] += ss[t + off]; qq[t] += qq[t + off]; }
        __syncthreads();
    }
    if (t == 0) {
        float mean = ss[0] * (1.f / NTOK);
        float var  = qq[0] * (1.f / NTOK) - mean * mean;
        float sc = g[c] * rsqrtf(var + EPSV);
        a[c] = sc;
        b[c] = be[c] - mean * sc;
    }
}

// ---------------- final affine to output ----------------
__global__ __launch_bounds__(256) void affine_out(
    const float* __restrict__ Y, const float* __restrict__ a,
    const float* __restrict__ b, float* __restrict__ out)
{
    int i = blockIdx.x * 256 + threadIdx.x;
    int c = i & (HID - 1);
    out[i] = Y[i] * a[c] + b[c];
}

// ---------------- launch ----------------
extern "C" void kernel_launch(void* const* d_in, const int* in_sizes, int n_in,
                              void* d_out, int out_size)
{
    const float* A  = (const float*)d_in[0];
    const float* h  = (const float*)d_in[1];
    const float* Wq = (const float*)d_in[2];
    const float* bq = (const float*)d_in[3];
    const float* Wk = (const float*)d_in[4];
    const float* bk = (const float*)d_in[5];
    const float* Wv = (const float*)d_in[6];
    const float* bv = (const float*)d_in[7];
    const float* Wo = (const float*)d_in[8];
    const float* bo = (const float*)d_in[9];
    const float* W1 = (const float*)d_in[10];
    const float* c1 = (const float*)d_in[11];
    const float* W2 = (const float*)d_in[12];
    const float* c2 = (const float*)d_in[13];
    const float* g1 = (const float*)d_in[14];
    const float* be1 = (const float*)d_in[15];
    const float* g2 = (const float*)d_in[16];
    const float* be2 = (const float*)d_in[17];
    float* out = (float*)d_out;

    float *Qp, *Kp, *Vp, *Ap, *y1p, *zp, *y2p, *a1p, *b1p, *a2p, *b2p;
    cudaGetSymbolAddress((void**)&Qp,  g_Q);
    cudaGetSymbolAddress((void**)&Kp,  g_K);
    cudaGetSymbolAddress((void**)&Vp,  g_V);
    cudaGetSymbolAddress((void**)&Ap,  g_attn);
    cudaGetSymbolAddress((void**)&y1p, g_y1);
    cudaGetSymbolAddress((void**)&zp,  g_z);
    cudaGetSymbolAddress((void**)&y2p, g_y2);
    cudaGetSymbolAddress((void**)&a1p, g_a1);
    cudaGetSymbolAddress((void**)&b1p, g_b1);
    cudaGetSymbolAddress((void**)&a2p, g_a2);
    cudaGetSymbolAddress((void**)&b2p, g_b2);

    const float scaling = 0.17677669529663687f;  // HD^-0.5

    dim3 blk(256);
    dim3 grid_qkv(HID / 64, NTOK / 64);

    // Q/K/V projections (q pre-scaled)
    gemm_fused<<<grid_qkv, blk>>>(h, Wq, bq, nullptr, nullptr, nullptr, nullptr, nullptr,
                                  Qp, NTOK, HID, HID, scaling, 0);
    gemm_fused<<<grid_qkv, blk>>>(h, Wk, bk, nullptr, nullptr, nullptr, nullptr, nullptr,
                                  Kp, NTOK, HID, HID, 1.f, 0);
    gemm_fused<<<grid_qkv, blk>>>(h, Wv, bv, nullptr, nullptr, nullptr, nullptr, nullptr,
                                  Vp, NTOK, HID, HID, 1.f, 0);

    // attention
    flash_attn<<<dim3(NTOK / 64, HEADS), blk>>>(Qp, Kp, Vp, A, Ap);

    // y1 = attn @ Wo^T + bo + h
    gemm_fused<<<grid_qkv, blk>>>(Ap, Wo, bo, h, nullptr, nullptr, nullptr, nullptr,
                                  y1p, NTOK, HID, HID, 1.f, 0);

    // bn1 stats -> (a1, b1)
    colstats<<<HID, 128>>>(y1p, g1, be1, a1p, b1p);

    // z = relu( bn1(y1) @ W1^T + c1 )   [N, 512]
    gemm_fused<<<dim3(2 * HID / 64, NTOK / 64), blk>>>(
        y1p, W1, c1, nullptr, a1p, b1p, nullptr, nullptr,
        zp, NTOK, HID, 2 * HID, 1.f, 1);

    // y2 = z @ W2^T + c2 + bn1(y1)
    gemm_fused<<<grid_qkv, blk>>>(zp, W2, c2, y1p, nullptr, nullptr, a1p, b1p,
                                  y2p, NTOK, 2 * HID, HID, 1.f, 0);

    // bn2 stats -> (a2, b2)
    colstats<<<HID, 128>>>(y2p, g2, be2, a2p, b2p);

    // out = bn2(y2)
    affine_out<<<NTOK * HID / 256, 256>>>(y2p, a2p, b2p, out);
}

// round 4
// speedup vs baseline: 1.6367x; 1.6367x over previous
#include <cuda_runtime.h>

#define NTOK 4096
#define HID  256
#define HEADS 8
#define HD   32
#define EPSV 1e-5f

// ---------------- scratch (no allocs allowed) ----------------
__device__ float g_Q[NTOK * HID];
__device__ float g_K[NTOK * HID];
__device__ float g_V[NTOK * HID];
__device__ float g_attn[NTOK * HID];
__device__ float g_y1[NTOK * HID];
__device__ float g_z[NTOK * 2 * HID];
__device__ float g_y2[NTOK * HID];
__device__ float g_a1[HID], g_b1[HID], g_a2[HID], g_b2[HID];

// ---------------- tf32 helpers ----------------
__device__ __forceinline__ unsigned f2tf(float f) {
    unsigned u;
    asm("cvt.rna.tf32.f32 %0, %1;" : "=r"(u) : "f"(f));
    return u;
}

// D += A(16x8) * B(8x8), tf32 inputs, f32 accum
__device__ __forceinline__ void mma8(float* c, const unsigned* a, unsigned b0, unsigned b1) {
    asm volatile(
        "mma.sync.aligned.m16n8k8.row.col.f32.tf32.tf32.f32 "
        "{%0,%1,%2,%3}, {%4,%5,%6,%7}, {%8,%9}, {%0,%1,%2,%3};\n"
        : "+f"(c[0]), "+f"(c[1]), "+f"(c[2]), "+f"(c[3])
        : "r"(a[0]), "r"(a[1]), "r"(a[2]), "r"(a[3]), "r"(b0), "r"(b1));
}

// ---------------- generic fused SGEMM (unchanged) ----------------
__global__ __launch_bounds__(256) void gemm_fused(
    const float* __restrict__ X, const float* __restrict__ W,
    const float* __restrict__ bias, const float* __restrict__ res,
    const float* __restrict__ ain, const float* __restrict__ bin,
    const float* __restrict__ ra, const float* __restrict__ rb,
    float* __restrict__ C, int M, int K, int Nout, float alpha, int relu)
{
    __shared__ float Xs[16][64];
    __shared__ float Ws[16][64];

    const int tid = threadIdx.x;
    const int tx = tid & 15, ty = tid >> 4;
    const int n0 = blockIdx.x * 64, m0 = blockIdx.y * 64;
    const int lr = tid >> 2;
    const int lk = (tid & 3) * 4;

    float acc[4][4] = {};

    for (int kt = 0; kt < K; kt += 16) {
        float4 xv = *(const float4*)&X[(size_t)(m0 + lr) * K + kt + lk];
        if (ain) {
            int c = kt + lk;
            xv.x = xv.x * ain[c + 0] + bin[c + 0];
            xv.y = xv.y * ain[c + 1] + bin[c + 1];
            xv.z = xv.z * ain[c + 2] + bin[c + 2];
            xv.w = xv.w * ain[c + 3] + bin[c + 3];
        }
        float4 wv = *(const float4*)&W[(size_t)(n0 + lr) * K + kt + lk];
        Xs[lk + 0][lr] = xv.x; Xs[lk + 1][lr] = xv.y;
        Xs[lk + 2][lr] = xv.z; Xs[lk + 3][lr] = xv.w;
        Ws[lk + 0][lr] = wv.x; Ws[lk + 1][lr] = wv.y;
        Ws[lk + 2][lr] = wv.z; Ws[lk + 3][lr] = wv.w;
        __syncthreads();

        #pragma unroll
        for (int kk = 0; kk < 16; kk++) {
            float4 a = *(const float4*)&Xs[kk][ty * 4];
            float4 b = *(const float4*)&Ws[kk][tx * 4];
            acc[0][0] += a.x * b.x; acc[0][1] += a.x * b.y; acc[0][2] += a.x * b.z; acc[0][3] += a.x * b.w;
            acc[1][0] += a.y * b.x; acc[1][1] += a.y * b.y; acc[1][2] += a.y * b.z; acc[1][3] += a.y * b.w;
            acc[2][0] += a.z * b.x; acc[2][1] += a.z * b.y; acc[2][2] += a.z * b.z; acc[2][3] += a.z * b.w;
            acc[3][0] += a.w * b.x; acc[3][1] += a.w * b.y; acc[3][2] += a.w * b.z; acc[3][3] += a.w * b.w;
        }
        __syncthreads();
    }

    #pragma unroll
    for (int i = 0; i < 4; i++) {
        int row = m0 + ty * 4 + i;
        #pragma unroll
        for (int j = 0; j < 4; j++) {
            int col = n0 + tx * 4 + j;
            float v = (acc[i][j] + bias[col]) * alpha;
            if (res) {
                float r = res[(size_t)row * Nout + col];
                if (ra) r = r * ra[col] + rb[col];
                v += r;
            }
            if (relu) v = fmaxf(v, 0.f);
            C[(size_t)row * Nout + col] = v;
        }
    }
}

// ---------------- tensor-core flash attention (tf32 mma) ----------------
// grid (NTOK/64, HEADS), 128 threads = 4 warps, each warp owns 16 q-rows.
// S(16x64) per warp via m16n8k8: 8 n-tiles x 4 k-steps.
// PV(16x32) via m16n8k8: 4 n-tiles x 8 k-steps, P staged through smem.
__global__ __launch_bounds__(128) void flash_attn_tc(
    const float* __restrict__ Q, const float* __restrict__ Kb,
    const float* __restrict__ Vb, const float* __restrict__ A,
    float* __restrict__ O)
{
    __shared__ float k_s[64 * 36];   // [key][d] stride 36  (bank 4r+c, conflict-free B-frags)
    __shared__ float v_s[64 * 40];   // [key][d] stride 40  (bank 8r+c, conflict-free B-frags)
    __shared__ float p_s[64 * 68];   // [row][key] stride 68 (bank 4r+c, conflict-free A-frags)

    const int tid  = threadIdx.x;
    const int warp = tid >> 5;
    const int lane = tid & 31;
    const int lq = lane >> 2;      // group id 0..7
    const int lr = lane & 3;       // thread-in-group 0..3
    const int h  = blockIdx.y;
    const int q0 = blockIdx.x * 64;
    const int wr = warp * 16;

    const float* __restrict__ Qh = Q  + (size_t)h * NTOK * HD;
    const float* __restrict__ Kh = Kb + (size_t)h * NTOK * HD;
    const float* __restrict__ Vh = Vb + (size_t)h * NTOK * HD;

    const int gr0 = q0 + wr + lq;     // global q row of fragment rows
    const int gr1 = gr0 + 8;

    // Q fragments (rounded tf32), kept in registers for whole kernel
    unsigned qa[4][4];
    #pragma unroll
    for (int ks = 0; ks < 4; ks++) {
        int c = ks * 8 + lr;
        qa[ks][0] = f2tf(Qh[(size_t)gr0 * HD + c]);
        qa[ks][1] = f2tf(Qh[(size_t)gr1 * HD + c]);
        qa[ks][2] = f2tf(Qh[(size_t)gr0 * HD + c + 4]);
        qa[ks][3] = f2tf(Qh[(size_t)gr1 * HD + c + 4]);
    }

    float m0 = -1e30f, m1 = -1e30f, l0 = 0.f, l1 = 0.f;
    float o[4][4] = {};              // 4 d-tiles; [0,1]=row gr0 cols c,c+1; [2,3]=row gr1

    const int ldrow  = tid >> 1;            // 0..63
    const int ldhalf = (tid & 1) * 16;      // 0 / 16

    for (int kt = 0; kt < NTOK / 64; kt++) {
        const int k0 = kt * 64;

        // adjacency prefetch (independent of smem): 8 n-tiles x 2 rows, float2 each
        float2 am0[8], am1[8];
        #pragma unroll
        for (int t = 0; t < 8; t++) {
            int c = k0 + t * 8 + lr * 2;
            am0[t] = *(const float2*)&A[(size_t)gr0 * NTOK + c];
            am1[t] = *(const float2*)&A[(size_t)gr1 * NTOK + c];
        }

        __syncthreads();   // prior PV reads of k_s/v_s/p_s done
        #pragma unroll
        for (int i = 0; i < 4; i++) {
            float4 kf = *(const float4*)&Kh[(size_t)(k0 + ldrow) * HD + ldhalf + i * 4];
            *(float4*)&k_s[ldrow * 36 + ldhalf + i * 4] = kf;
            float4 vf = *(const float4*)&Vh[(size_t)(k0 + ldrow) * HD + ldhalf + i * 4];
            *(float4*)&v_s[ldrow * 40 + ldhalf + i * 4] = vf;
        }
        __syncthreads();

        // ---- QK^T: S(16x64) ----
        float s[8][4] = {};
        #pragma unroll
        for (int ks = 0; ks < 4; ks++) {
            #pragma unroll
            for (int t = 0; t < 8; t++) {
                unsigned b0 = __float_as_uint(k_s[(t * 8 + lq) * 36 + ks * 8 + lr]);
                unsigned b1 = __float_as_uint(k_s[(t * 8 + lq) * 36 + ks * 8 + lr + 4]);
                mma8(s[t], qa[ks], b0, b1);
            }
        }

        // ---- mask + online softmax ----
        float mt0 = -1e30f, mt1 = -1e30f;
        #pragma unroll
        for (int t = 0; t < 8; t++) {
            s[t][0] *= am0[t].x; s[t][1] *= am0[t].y;
            s[t][2] *= am1[t].x; s[t][3] *= am1[t].y;
            mt0 = fmaxf(mt0, fmaxf(s[t][0], s[t][1]));
            mt1 = fmaxf(mt1, fmaxf(s[t][2], s[t][3]));
        }
        #pragma unroll
        for (int off = 1; off <= 2; off <<= 1) {
            mt0 = fmaxf(mt0, __shfl_xor_sync(0xffffffffu, mt0, off));
            mt1 = fmaxf(mt1, __shfl_xor_sync(0xffffffffu, mt1, off));
        }
        float mn0 = fmaxf(m0, mt0), mn1 = fmaxf(m1, mt1);
        float cor0 = __expf(m0 - mn0), cor1 = __expf(m1 - mn1);
        l0 *= cor0; l1 *= cor1;
        #pragma unroll
        for (int t = 0; t < 4; t++) {
            o[t][0] *= cor0; o[t][1] *= cor0;
            o[t][2] *= cor1; o[t][3] *= cor1;
        }
        m0 = mn0; m1 = mn1;

        float rs0 = 0.f, rs1 = 0.f;
        #pragma unroll
        for (int t = 0; t < 8; t++) {
            float p0 = __expf(s[t][0] - mn0);
            float p1 = __expf(s[t][1] - mn0);
            float p2 = __expf(s[t][2] - mn1);
            float p3 = __expf(s[t][3] - mn1);
            rs0 += p0 + p1; rs1 += p2 + p3;
            // store P rounded-to-tf32 so PV truncation is exact
            float2 w0 = make_float2(__uint_as_float(f2tf(p0)), __uint_as_float(f2tf(p1)));
            float2 w1 = make_float2(__uint_as_float(f2tf(p2)), __uint_as_float(f2tf(p3)));
            *(float2*)&p_s[(wr + lq) * 68 + t * 8 + lr * 2]     = w0;
            *(float2*)&p_s[(wr + lq + 8) * 68 + t * 8 + lr * 2] = w1;
        }
        #pragma unroll
        for (int off = 1; off <= 2; off <<= 1) {
            rs0 += __shfl_xor_sync(0xffffffffu, rs0, off);
            rs1 += __shfl_xor_sync(0xffffffffu, rs1, off);
        }
        l0 += rs0; l1 += rs1;
        __syncwarp();   // p_s is warp-private: visibility only

        // ---- PV: O(16x32) += P(16x64) * V(64x32) ----
        #pragma unroll
        for (int ks = 0; ks < 8; ks++) {
            unsigned pa[4];
            pa[0] = __float_as_uint(p_s[(wr + lq) * 68 + ks * 8 + lr]);
            pa[1] = __float_as_uint(p_s[(wr + lq + 8) * 68 + ks * 8 + lr]);
            pa[2] = __float_as_uint(p_s[(wr + lq) * 68 + ks * 8 + lr + 4]);
            pa[3] = __float_as_uint(p_s[(wr + lq + 8) * 68 + ks * 8 + lr + 4]);
            #pragma unroll
            for (int t = 0; t < 4; t++) {
                unsigned b0 = __float_as_uint(v_s[(ks * 8 + lr) * 40 + t * 8 + lq]);
                unsigned b1 = __float_as_uint(v_s[(ks * 8 + lr + 4) * 40 + t * 8 + lq]);
                mma8(o[t], pa, b0, b1);
            }
        }
    }

    // ---- epilogue ----
    float inv0 = 1.f / l0, inv1 = 1.f / l1;
    float* __restrict__ Oh = O + (size_t)h * NTOK * HD;
    #pragma unroll
    for (int t = 0; t < 4; t++) {
        int c = t * 8 + lr * 2;
        *(float2*)&Oh[(size_t)gr0 * HD + c] = make_float2(o[t][0] * inv0, o[t][1] * inv0);
        *(float2*)&Oh[(size_t)gr1 * HD + c] = make_float2(o[t][2] * inv1, o[t][3] * inv1);
    }
}

// ---------------- batchnorm column stats -> fused scale/shift ----------------
__global__ __launch_bounds__(128) void colstats(
    const float* __restrict__ Y, const float* __restrict__ g,
    const float* __restrict__ be, float* __restrict__ a, float* __restrict__ b)
{
    const int c = blockIdx.x;
    const int t = threadIdx.x;
    float s = 0.f, sq = 0.f;
    for (int r = t; r < NTOK; r += 128) {
        float v = Y[(size_t)r * HID + c];
        s += v; sq += v * v;
    }
    __shared__ float ss[128], qq[128];
    ss[t] = s; qq[t] = sq;
    __syncthreads();
    for (int off = 64; off; off >>= 1) {
        if (t < off) { ss[t] += ss[t + off]; qq[t] += qq[t + off]; }
        __syncthreads();
    }
    if (t == 0) {
        float mean = ss[0] * (1.f / NTOK);
        float var  = qq[0] * (1.f / NTOK) - mean * mean;
        float sc = g[c] * rsqrtf(var + EPSV);
        a[c] = sc;
        b[c] = be[c] - mean * sc;
    }
}

// ---------------- final affine to output ----------------
__global__ __launch_bounds__(256) void affine_out(
    const float* __restrict__ Y, const float* __restrict__ a,
    const float* __restrict__ b, float* __restrict__ out)
{
    int i = blockIdx.x * 256 + threadIdx.x;
    int c = i & (HID - 1);
    out[i] = Y[i] * a[c] + b[c];
}

// ---------------- launch ----------------
extern "C" void kernel_launch(void* const* d_in, const int* in_sizes, int n_in,
                              void* d_out, int out_size)
{
    const float* A  = (const float*)d_in[0];
    const float* h  = (const float*)d_in[1];
    const float* Wq = (const float*)d_in[2];
    const float* bq = (const float*)d_in[3];
    const float* Wk = (const float*)d_in[4];
    const float* bk = (const float*)d_in[5];
    const float* Wv = (const float*)d_in[6];
    const float* bv = (const float*)d_in[7];
    const float* Wo = (const float*)d_in[8];
    const float* bo = (const float*)d_in[9];
    const float* W1 = (const float*)d_in[10];
    const float* c1 = (const float*)d_in[11];
    const float* W2 = (const float*)d_in[12];
    const float* c2 = (const float*)d_in[13];
    const float* g1 = (const float*)d_in[14];
    const float* be1 = (const float*)d_in[15];
    const float* g2 = (const float*)d_in[16];
    const float* be2 = (const float*)d_in[17];
    float* out = (float*)d_out;

    float *Qp, *Kp, *Vp, *Ap, *y1p, *zp, *y2p, *a1p, *b1p, *a2p, *b2p;
    cudaGetSymbolAddress((void**)&Qp,  g_Q);
    cudaGetSymbolAddress((void**)&Kp,  g_K);
    cudaGetSymbolAddress((void**)&Vp,  g_V);
    cudaGetSymbolAddress((void**)&Ap,  g_attn);
    cudaGetSymbolAddress((void**)&y1p, g_y1);
    cudaGetSymbolAddress((void**)&zp,  g_z);
    cudaGetSymbolAddress((void**)&y2p, g_y2);
    cudaGetSymbolAddress((void**)&a1p, g_a1);
    cudaGetSymbolAddress((void**)&b1p, g_b1);
    cudaGetSymbolAddress((void**)&a2p, g_a2);
    cudaGetSymbolAddress((void**)&b2p, g_b2);

    const float scaling = 0.17677669529663687f;  // HD^-0.5

    dim3 blk(256);
    dim3 grid_qkv(HID / 64, NTOK / 64);

    gemm_fused<<<grid_qkv, blk>>>(h, Wq, bq, nullptr, nullptr, nullptr, nullptr, nullptr,
                                  Qp, NTOK, HID, HID, scaling, 0);
    gemm_fused<<<grid_qkv, blk>>>(h, Wk, bk, nullptr, nullptr, nullptr, nullptr, nullptr,
                                  Kp, NTOK, HID, HID, 1.f, 0);
    gemm_fused<<<grid_qkv, blk>>>(h, Wv, bv, nullptr, nullptr, nullptr, nullptr, nullptr,
                                  Vp, NTOK, HID, HID, 1.f, 0);

    flash_attn_tc<<<dim3(NTOK / 64, HEADS), 128>>>(Qp, Kp, Vp, A, Ap);

    gemm_fused<<<grid_qkv, blk>>>(Ap, Wo, bo, h, nullptr, nullptr, nullptr, nullptr,
                                  y1p, NTOK, HID, HID, 1.f, 0);

    colstats<<<HID, 128>>>(y1p, g1, be1, a1p, b1p);

    gemm_fused<<<dim3(2 * HID / 64, NTOK / 64), blk>>>(
        y1p, W1, c1, nullptr, a1p, b1p, nullptr, nullptr,
        zp, NTOK, HID, 2 * HID, 1.f, 1);

    gemm_fused<<<grid_qkv, blk>>>(zp, W2, c2, y1p, nullptr, nullptr, a1p, b1p,
                                  y2p, NTOK, 2 * HID, HID, 1.f, 0);

    colstats<<<HID, 128>>>(y2p, g2, be2, a2p, b2p);

    affine_out<<<NTOK * HID / 256, 256>>>(y2p, a2p, b2p, out);
}

// round 10
// speedup vs baseline: 2.7819x; 1.6997x over previous
#include <cuda_runtime.h>
#include <cuda_fp16.h>
#include <cstring>

#define NTOK 4096
#define HID  256
#define HEADS 8
#define HD   32
#define EPSV 1e-5f

// ---------------- scratch (no allocs allowed) ----------------
__device__ float g_Q[NTOK * HID];
__device__ float g_K[NTOK * HID];
__device__ float g_V[NTOK * HID];
__device__ float g_attn[NTOK * HID];
__device__ float g_y1[NTOK * HID];
__device__ float g_z[NTOK * 2 * HID];
__device__ float g_y2[NTOK * HID];
__device__ float g_a1[HID], g_b1[HID], g_a2[HID], g_b2[HID];

// ---------------- mma helpers ----------------
__device__ __forceinline__ unsigned h2u(__half2 h) {
    unsigned u;
    memcpy(&u, &h, 4);
    return u;
}

__device__ __forceinline__ unsigned packh2(float a, float b) {
    return h2u(__floats2half2_rn(a, b));
}

// D += A(16x16) * B(16x8), fp16 inputs, f32 accum
__device__ __forceinline__ void mma16(float* c, const unsigned* a, unsigned b0, unsigned b1) {
    asm volatile(
        "mma.sync.aligned.m16n8k16.row.col.f32.f16.f16.f32 "
        "{%0,%1,%2,%3}, {%4,%5,%6,%7}, {%8,%9}, {%0,%1,%2,%3};\n"
        : "+f"(c[0]), "+f"(c[1]), "+f"(c[2]), "+f"(c[3])
        : "r"(a[0]), "r"(a[1]), "r"(a[2]), "r"(a[3]), "r"(b0), "r"(b1));
}

__device__ __forceinline__ unsigned smem_u32(const void* p) {
    return (unsigned)__cvta_generic_to_shared(p);
}

__device__ __forceinline__ void ldm_x4(unsigned* r, unsigned addr) {
    asm volatile("ldmatrix.sync.aligned.m8n8.x4.shared.b16 {%0,%1,%2,%3}, [%4];"
                 : "=r"(r[0]), "=r"(r[1]), "=r"(r[2]), "=r"(r[3]) : "r"(addr));
}

__device__ __forceinline__ void ldm_x4_t(unsigned* r, unsigned addr) {
    asm volatile("ldmatrix.sync.aligned.m8n8.x4.trans.shared.b16 {%0,%1,%2,%3}, [%4];"
                 : "=r"(r[0]), "=r"(r[1]), "=r"(r[2]), "=r"(r[3]) : "r"(addr));
}

// ---------------- fp16 tensor-core fused GEMM ----------------
// C[M,Nout] = relu?( alpha*(X' @ W^T + bias) + res' )
//   X'   = ain ? X*ain[kcol]+bin[kcol] : X   (applied in fp32 before fp16 cvt)
//   res' = res ? (ra ? res*ra[col]+rb[col] : res) : 0   (fp32)
// 128 threads = 4 warps; CTA tile 64x64, BK=32; warp owns 16 rows x 64 cols.
__global__ __launch_bounds__(128) void gemm_h(
    const float* __restrict__ X, const float* __restrict__ W,
    const float* __restrict__ bias, const float* __restrict__ res,
    const float* __restrict__ ain, const float* __restrict__ bin,
    const float* __restrict__ ra, const float* __restrict__ rb,
    float* __restrict__ C, int M, int K, int Nout, float alpha, int relu)
{
    __shared__ __align__(16) __half x_s[64 * 40];
    __shared__ __align__(16) __half w_s[64 * 40];

    const int tid  = threadIdx.x;
    const int warp = tid >> 5;
    const int lane = tid & 31;
    const int lq = lane >> 2, lr = lane & 3;
    const int n0 = blockIdx.x * 64, m0 = blockIdx.y * 64;
    const int wr = warp * 16;

    float acc[8][4] = {};

    const int ldrow = tid >> 1;
    const int ldc0  = (tid & 1) * 16;

    for (int kt = 0; kt < K; kt += 32) {
        __syncthreads();
        #pragma unroll
        for (int i = 0; i < 4; i++) {
            int c = kt + ldc0 + i * 4;
            float4 xv = *(const float4*)&X[(size_t)(m0 + ldrow) * K + c];
            if (ain) {
                xv.x = xv.x * ain[c + 0] + bin[c + 0];
                xv.y = xv.y * ain[c + 1] + bin[c + 1];
                xv.z = xv.z * ain[c + 2] + bin[c + 2];
                xv.w = xv.w * ain[c + 3] + bin[c + 3];
            }
            float4 wv = *(const float4*)&W[(size_t)(n0 + ldrow) * K + c];
            *(__half2*)&x_s[ldrow * 40 + ldc0 + i * 4]     = __floats2half2_rn(xv.x, xv.y);
            *(__half2*)&x_s[ldrow * 40 + ldc0 + i * 4 + 2] = __floats2half2_rn(xv.z, xv.w);
            *(__half2*)&w_s[ldrow * 40 + ldc0 + i * 4]     = __floats2half2_rn(wv.x, wv.y);
            *(__half2*)&w_s[ldrow * 40 + ldc0 + i * 4 + 2] = __floats2half2_rn(wv.z, wv.w);
        }
        __syncthreads();

        // A fragments: X rows wr..wr+16, k-chunks of 16
        unsigned xa[2][4];
        #pragma unroll
        for (int kc = 0; kc < 2; kc++)
            ldm_x4(xa[kc], smem_u32(&x_s[(wr + (lane & 15)) * 40 + kc * 16 + (lane >> 4) * 8]));

        #pragma unroll
        for (int t = 0; t < 8; t++) {
            // B fragments: W rows 8t..8t+8 (output cols), k 0..32
            unsigned kb[4];
            ldm_x4(kb, smem_u32(&w_s[(8 * t + (lane & 7)) * 40 + (lane >> 3) * 8]));
            mma16(acc[t], xa[0], kb[0], kb[1]);
            mma16(acc[t], xa[1], kb[2], kb[3]);
        }
    }

    // epilogue: acc[t][0,1] -> row m0+wr+lq, cols n0+8t+2lr(+1); [2,3] -> row +8
    const int r0 = m0 + wr + lq;
    const int r1 = r0 + 8;
    #pragma unroll
    for (int t = 0; t < 8; t++) {
        #pragma unroll
        for (int j = 0; j < 2; j++) {
            int cc = n0 + t * 8 + 2 * lr + j;
            float b = bias[cc];
            float v0 = (acc[t][j]     + b) * alpha;
            float v1 = (acc[t][2 + j] + b) * alpha;
            if (res) {
                float q0 = res[(size_t)r0 * Nout + cc];
                float q1 = res[(size_t)r1 * Nout + cc];
                if (ra) {
                    float sa = ra[cc], sb = rb[cc];
                    q0 = q0 * sa + sb;
                    q1 = q1 * sa + sb;
                }
                v0 += q0; v1 += q1;
            }
            if (relu) { v0 = fmaxf(v0, 0.f); v1 = fmaxf(v1, 0.f); }
            C[(size_t)r0 * Nout + cc] = v0;
            C[(size_t)r1 * Nout + cc] = v1;
        }
    }
}

// ---------------- fp16 tensor-core flash attention ----------------
// grid (NTOK/64, HEADS), 128 threads = 4 warps, warp owns 16 q-rows.
// QK^T: m16n8k16, K frags via ldmatrix.x4 (non-trans).
// PV:   m16n8k16, P stays in registers (S-accum layout == A-frag layout),
//       V frags via ldmatrix.x4.trans.
__global__ __launch_bounds__(128) void flash_attn_h(
    const float* __restrict__ Q, const float* __restrict__ Kb,
    const float* __restrict__ Vb, const float* __restrict__ A,
    float* __restrict__ O)
{
    __shared__ __align__(16) __half k_s[64 * 40];
    __shared__ __align__(16) __half v_s[64 * 40];

    const int tid  = threadIdx.x;
    const int warp = tid >> 5;
    const int lane = tid & 31;
    const int lq = lane >> 2;      // group 0..7
    const int lr = lane & 3;       // 0..3
    const int h  = blockIdx.y;
    const int q0 = blockIdx.x * 64;
    const int wr = warp * 16;

    const float* __restrict__ Qh = Q  + (size_t)h * NTOK * HD;
    const float* __restrict__ Kh = Kb + (size_t)h * NTOK * HD;
    const float* __restrict__ Vh = Vb + (size_t)h * NTOK * HD;

    const int gr0 = q0 + wr + lq;
    const int gr1 = gr0 + 8;

    // Q A-fragments (2 k-chunks of 16), fp16, register-resident
    unsigned qa[2][4];
    #pragma unroll
    for (int kc = 0; kc < 2; kc++) {
        int c = kc * 16 + 2 * lr;
        qa[kc][0] = packh2(Qh[(size_t)gr0 * HD + c],     Qh[(size_t)gr0 * HD + c + 1]);
        qa[kc][1] = packh2(Qh[(size_t)gr1 * HD + c],     Qh[(size_t)gr1 * HD + c + 1]);
        qa[kc][2] = packh2(Qh[(size_t)gr0 * HD + c + 8], Qh[(size_t)gr0 * HD + c + 9]);
        qa[kc][3] = packh2(Qh[(size_t)gr1 * HD + c + 8], Qh[(size_t)gr1 * HD + c + 9]);
    }

    float m0 = -1e30f, m1 = -1e30f, l0 = 0.f, l1 = 0.f;
    float o[4][4] = {};

    const int ldrow = tid >> 1;
    const int ldc0  = (tid & 1) * 16;

    for (int kt = 0; kt < NTOK / 64; kt++) {
        const int k0 = kt * 64;

        // adjacency prefetch (gmem, overlaps smem fill)
        float2 am0[8], am1[8];
        #pragma unroll
        for (int t = 0; t < 8; t++) {
            int c = k0 + t * 8 + lr * 2;
            am0[t] = *(const float2*)&A[(size_t)gr0 * NTOK + c];
            am1[t] = *(const float2*)&A[(size_t)gr1 * NTOK + c];
        }

        __syncthreads();
        #pragma unroll
        for (int i = 0; i < 4; i++) {
            float4 kf = *(const float4*)&Kh[(size_t)(k0 + ldrow) * HD + ldc0 + i * 4];
            float4 vf = *(const float4*)&Vh[(size_t)(k0 + ldrow) * HD + ldc0 + i * 4];
            *(__half2*)&k_s[ldrow * 40 + ldc0 + i * 4]     = __floats2half2_rn(kf.x, kf.y);
            *(__half2*)&k_s[ldrow * 40 + ldc0 + i * 4 + 2] = __floats2half2_rn(kf.z, kf.w);
            *(__half2*)&v_s[ldrow * 40 + ldc0 + i * 4]     = __floats2half2_rn(vf.x, vf.y);
            *(__half2*)&v_s[ldrow * 40 + ldc0 + i * 4 + 2] = __floats2half2_rn(vf.z, vf.w);
        }
        __syncthreads();

        // ---- QK^T: S(16x64) ----
        float s[8][4] = {};
        #pragma unroll
        for (int t = 0; t < 8; t++) {
            unsigned kb[4];
            unsigned addr = smem_u32(&k_s[(8 * t + (lane & 7)) * 40 + (lane >> 3) * 8]);
            ldm_x4(kb, addr);
            mma16(s[t], qa[0], kb[0], kb[1]);
            mma16(s[t], qa[1], kb[2], kb[3]);
        }

        // ---- mask + online softmax ----
        float mt0 = -1e30f, mt1 = -1e30f;
        #pragma unroll
        for (int t = 0; t < 8; t++) {
            s[t][0] *= am0[t].x; s[t][1] *= am0[t].y;
            s[t][2] *= am1[t].x; s[t][3] *= am1[t].y;
            mt0 = fmaxf(mt0, fmaxf(s[t][0], s[t][1]));
            mt1 = fmaxf(mt1, fmaxf(s[t][2], s[t][3]));
        }
        #pragma unroll
        for (int off = 1; off <= 2; off <<= 1) {
            mt0 = fmaxf(mt0, __shfl_xor_sync(0xffffffffu, mt0, off));
            mt1 = fmaxf(mt1, __shfl_xor_sync(0xffffffffu, mt1, off));
        }
        float mn0 = fmaxf(m0, mt0), mn1 = fmaxf(m1, mt1);
        float cor0 = __expf(m0 - mn0), cor1 = __expf(m1 - mn1);
        l0 *= cor0; l1 *= cor1;
        #pragma unroll
        for (int t = 0; t < 4; t++) {
            o[t][0] *= cor0; o[t][1] *= cor0;
            o[t][2] *= cor1; o[t][3] *= cor1;
        }
        m0 = mn0; m1 = mn1;

        float rs0 = 0.f, rs1 = 0.f;
        #pragma unroll
        for (int t = 0; t < 8; t++) {
            s[t][0] = __expf(s[t][0] - mn0);
            s[t][1] = __expf(s[t][1] - mn0);
            s[t][2] = __expf(s[t][2] - mn1);
            s[t][3] = __expf(s[t][3] - mn1);
            rs0 += s[t][0] + s[t][1];
            rs1 += s[t][2] + s[t][3];
        }
        #pragma unroll
        for (int off = 1; off <= 2; off <<= 1) {
            rs0 += __shfl_xor_sync(0xffffffffu, rs0, off);
            rs1 += __shfl_xor_sync(0xffffffffu, rs1, off);
        }
        l0 += rs0; l1 += rs1;

        // ---- PV: O(16x32) += P(16x64) * V(64x32), P in registers ----
        #pragma unroll
        for (int kc = 0; kc < 4; kc++) {
            unsigned pa[4];
            pa[0] = packh2(s[2 * kc][0],     s[2 * kc][1]);
            pa[1] = packh2(s[2 * kc][2],     s[2 * kc][3]);
            pa[2] = packh2(s[2 * kc + 1][0], s[2 * kc + 1][1]);
            pa[3] = packh2(s[2 * kc + 1][2], s[2 * kc + 1][3]);
            #pragma unroll
            for (int tp = 0; tp < 2; tp++) {
                unsigned vb[4];
                int key = 16 * kc + ((lane >> 3) & 1) * 8 + (lane & 7);
                int dof = 16 * tp + (lane >> 4) * 8;
                unsigned addr = smem_u32(&v_s[key * 40 + dof]);
                ldm_x4_t(vb, addr);
                mma16(o[2 * tp],     pa, vb[0], vb[1]);
                mma16(o[2 * tp + 1], pa, vb[2], vb[3]);
            }
        }
    }

    // ---- epilogue ----
    float inv0 = 1.f / l0, inv1 = 1.f / l1;
    float* __restrict__ Oh = O + (size_t)h * NTOK * HD;
    #pragma unroll
    for (int t = 0; t < 4; t++) {
        int c = t * 8 + lr * 2;
        *(float2*)&Oh[(size_t)gr0 * HD + c] = make_float2(o[t][0] * inv0, o[t][1] * inv0);
        *(float2*)&Oh[(size_t)gr1 * HD + c] = make_float2(o[t][2] * inv1, o[t][3] * inv1);
    }
}

// ---------------- batchnorm column stats -> fused scale/shift ----------------
__global__ __launch_bounds__(128) void colstats(
    const float* __restrict__ Y, const float* __restrict__ g,
    const float* __restrict__ be, float* __restrict__ a, float* __restrict__ b)
{
    const int c = blockIdx.x;
    const int t = threadIdx.x;
    float s = 0.f, sq = 0.f;
    for (int r = t; r < NTOK; r += 128) {
        float v = Y[(size_t)r * HID + c];
        s += v; sq += v * v;
    }
    __shared__ float ss[128], qq[128];
    ss[t] = s; qq[t] = sq;
    __syncthreads();
    for (int off = 64; off; off >>= 1) {
        if (t < off) { ss[t] += ss[t + off]; qq[t] += qq[t + off]; }
        __syncthreads();
    }
    if (t == 0) {
        float mean = ss[0] * (1.f / NTOK);
        float var  = qq[0] * (1.f / NTOK) - mean * mean;
        float sc = g[c] * rsqrtf(var + EPSV);
        a[c] = sc;
        b[c] = be[c] - mean * sc;
    }
}

// ---------------- final affine to output ----------------
__global__ __launch_bounds__(256) void affine_out(
    const float* __restrict__ Y, const float* __restrict__ a,
    const float* __restrict__ b, float* __restrict__ out)
{
    int i = blockIdx.x * 256 + threadIdx.x;
    int c = i & (HID - 1);
    out[i] = Y[i] * a[c] + b[c];
}

// ---------------- launch ----------------
extern "C" void kernel_launch(void* const* d_in, const int* in_sizes, int n_in,
                              void* d_out, int out_size)
{
    const float* A  = (const float*)d_in[0];
    const float* h  = (const float*)d_in[1];
    const float* Wq = (const float*)d_in[2];
    const float* bq = (const float*)d_in[3];
    const float* Wk = (const float*)d_in[4];
    const float* bk = (const float*)d_in[5];
    const float* Wv = (const float*)d_in[6];
    const float* bv = (const float*)d_in[7];
    const float* Wo = (const float*)d_in[8];
    const float* bo = (const float*)d_in[9];
    const float* W1 = (const float*)d_in[10];
    const float* c1 = (const float*)d_in[11];
    const float* W2 = (const float*)d_in[12];
    const float* c2 = (const float*)d_in[13];
    const float* g1 = (const float*)d_in[14];
    const float* be1 = (const float*)d_in[15];
    const float* g2 = (const float*)d_in[16];
    const float* be2 = (const float*)d_in[17];
    float* out = (float*)d_out;

    float *Qp, *Kp, *Vp, *Ap, *y1p, *zp, *y2p, *a1p, *b1p, *a2p, *b2p;
    cudaGetSymbolAddress((void**)&Qp,  g_Q);
    cudaGetSymbolAddress((void**)&Kp,  g_K);
    cudaGetSymbolAddress((void**)&Vp,  g_V);
    cudaGetSymbolAddress((void**)&Ap,  g_attn);
    cudaGetSymbolAddress((void**)&y1p, g_y1);
    cudaGetSymbolAddress((void**)&zp,  g_z);
    cudaGetSymbolAddress((void**)&y2p, g_y2);
    cudaGetSymbolAddress((void**)&a1p, g_a1);
    cudaGetSymbolAddress((void**)&b1p, g_b1);
    cudaGetSymbolAddress((void**)&a2p, g_a2);
    cudaGetSymbolAddress((void**)&b2p, g_b2);

    const float scaling = 0.17677669529663687f;  // HD^-0.5

    dim3 grid_qkv(HID / 64, NTOK / 64);

    // Q/K/V projections (q pre-scaled)
    gemm_h<<<grid_qkv, 128>>>(h, Wq, bq, nullptr, nullptr, nullptr, nullptr, nullptr,
                              Qp, NTOK, HID, HID, scaling, 0);
    gemm_h<<<grid_qkv, 128>>>(h, Wk, bk, nullptr, nullptr, nullptr, nullptr, nullptr,
                              Kp, NTOK, HID, HID, 1.f, 0);
    gemm_h<<<grid_qkv, 128>>>(h, Wv, bv, nullptr, nullptr, nullptr, nullptr, nullptr,
                              Vp, NTOK, HID, HID, 1.f, 0);

    flash_attn_h<<<dim3(NTOK / 64, HEADS), 128>>>(Qp, Kp, Vp, A, Ap);

    // y1 = attn @ Wo^T + bo + h
    gemm_h<<<grid_qkv, 128>>>(Ap, Wo, bo, h, nullptr, nullptr, nullptr, nullptr,
                              y1p, NTOK, HID, HID, 1.f, 0);

    colstats<<<HID, 128>>>(y1p, g1, be1, a1p, b1p);

    // z = relu( bn1(y1) @ W1^T + c1 )   [N, 512]
    gemm_h<<<dim3(2 * HID / 64, NTOK / 64), 128>>>(
        y1p, W1, c1, nullptr, a1p, b1p, nullptr, nullptr,
        zp, NTOK, HID, 2 * HID, 1.f, 1);

    // y2 = z @ W2^T + c2 + bn1(y1)
    gemm_h<<<grid_qkv, 128>>>(zp, W2, c2, y1p, nullptr, nullptr, a1p, b1p,
                              y2p, NTOK, 2 * HID, HID, 1.f, 0);

    colstats<<<HID, 128>>>(y2p, g2, be2, a2p, b2p);

    affine_out<<<NTOK * HID / 256, 256>>>(y2p, a2p, b2p, out);
}

// round 14
// speedup vs baseline: 3.4294x; 1.2328x over previous
#include <cuda_runtime.h>
#include <cuda_fp16.h>
#include <cstring>

#define NTOK 4096
#define HID  256
#define HEADS 8
#define HD   32
#define EPSV 1e-5f

// ---------------- scratch (no allocs allowed) ----------------
__device__ __half g_Qh[NTOK * HID];
__device__ __half g_Kh[NTOK * HID];
__device__ __half g_Vh[NTOK * HID];
__device__ __half g_Oh[NTOK * HID];
__device__ float g_y1[NTOK * HID];
__device__ float g_z[NTOK * 2 * HID];
__device__ float g_y2[NTOK * HID];
__device__ float g_a1[HID], g_b1[HID], g_a2[HID], g_b2[HID];

// ---------------- mma helpers ----------------
__device__ __forceinline__ unsigned h2u(__half2 h) {
    unsigned u;
    memcpy(&u, &h, 4);
    return u;
}

__device__ __forceinline__ unsigned packh2(float a, float b) {
    return h2u(__floats2half2_rn(a, b));
}

// D += A(16x16) * B(16x8), fp16 inputs, f32 accum
__device__ __forceinline__ void mma16(float* c, const unsigned* a, unsigned b0, unsigned b1) {
    asm volatile(
        "mma.sync.aligned.m16n8k16.row.col.f32.f16.f16.f32 "
        "{%0,%1,%2,%3}, {%4,%5,%6,%7}, {%8,%9}, {%0,%1,%2,%3};\n"
        : "+f"(c[0]), "+f"(c[1]), "+f"(c[2]), "+f"(c[3])
        : "r"(a[0]), "r"(a[1]), "r"(a[2]), "r"(a[3]), "r"(b0), "r"(b1));
}

__device__ __forceinline__ unsigned smem_u32(const void* p) {
    return (unsigned)__cvta_generic_to_shared(p);
}

__device__ __forceinline__ void ldm_x4(unsigned* r, unsigned addr) {
    asm volatile("ldmatrix.sync.aligned.m8n8.x4.shared.b16 {%0,%1,%2,%3}, [%4];"
                 : "=r"(r[0]), "=r"(r[1]), "=r"(r[2]), "=r"(r[3]) : "r"(addr));
}

__device__ __forceinline__ void ldm_x4_t(unsigned* r, unsigned addr) {
    asm volatile("ldmatrix.sync.aligned.m8n8.x4.trans.shared.b16 {%0,%1,%2,%3}, [%4];"
                 : "=r"(r[0]), "=r"(r[1]), "=r"(r[2]), "=r"(r[3]) : "r"(addr));
}

// ---------------- fused QKV projection, fp16 output ----------------
// grid (HID/64, NTOK/64, 3); z=0:Q (alpha=scaling), z=1:K, z=2:V.
__global__ __launch_bounds__(128) void gemm_qkv(
    const float* __restrict__ X,
    const float* __restrict__ Wq, const float* __restrict__ bq,
    const float* __restrict__ Wk, const float* __restrict__ bk,
    const float* __restrict__ Wv, const float* __restrict__ bv,
    __half* __restrict__ Qh, __half* __restrict__ Kh, __half* __restrict__ Vh,
    float scaling)
{
    const int z = blockIdx.z;
    const float* W    = (z == 0) ? Wq : (z == 1) ? Wk : Wv;
    const float* bias = (z == 0) ? bq : (z == 1) ? bk : bv;
    __half* Ch        = (z == 0) ? Qh : (z == 1) ? Kh : Vh;
    const float alpha = (z == 0) ? scaling : 1.f;
    const int K = HID, Nout = HID;

    __shared__ __align__(16) __half x_s[64 * 40];
    __shared__ __align__(16) __half w_s[64 * 40];

    const int tid  = threadIdx.x;
    const int warp = tid >> 5;
    const int lane = tid & 31;
    const int lq = lane >> 2, lr = lane & 3;
    const int n0 = blockIdx.x * 64, m0 = blockIdx.y * 64;
    const int wr = warp * 16;

    float acc[8][4] = {};
    const int ldrow = tid >> 1;
    const int ldc0  = (tid & 1) * 16;

    for (int kt = 0; kt < K; kt += 32) {
        __syncthreads();
        #pragma unroll
        for (int i = 0; i < 4; i++) {
            int c = kt + ldc0 + i * 4;
            float4 xv = *(const float4*)&X[(size_t)(m0 + ldrow) * K + c];
            float4 wv = *(const float4*)&W[(size_t)(n0 + ldrow) * K + c];
            *(__half2*)&x_s[ldrow * 40 + ldc0 + i * 4]     = __floats2half2_rn(xv.x, xv.y);
            *(__half2*)&x_s[ldrow * 40 + ldc0 + i * 4 + 2] = __floats2half2_rn(xv.z, xv.w);
            *(__half2*)&w_s[ldrow * 40 + ldc0 + i * 4]     = __floats2half2_rn(wv.x, wv.y);
            *(__half2*)&w_s[ldrow * 40 + ldc0 + i * 4 + 2] = __floats2half2_rn(wv.z, wv.w);
        }
        __syncthreads();

        unsigned xa[2][4];
        #pragma unroll
        for (int kc = 0; kc < 2; kc++)
            ldm_x4(xa[kc], smem_u32(&x_s[(wr + (lane & 15)) * 40 + kc * 16 + (lane >> 4) * 8]));

        #pragma unroll
        for (int t = 0; t < 8; t++) {
            unsigned kb[4];
            ldm_x4(kb, smem_u32(&w_s[(8 * t + (lane & 7)) * 40 + (lane >> 3) * 8]));
            mma16(acc[t], xa[0], kb[0], kb[1]);
            mma16(acc[t], xa[1], kb[2], kb[3]);
        }
    }

    const int r0 = m0 + wr + lq;
    const int r1 = r0 + 8;
    #pragma unroll
    for (int t = 0; t < 8; t++) {
        int cc = n0 + t * 8 + 2 * lr;
        float b0 = bias[cc], b1 = bias[cc + 1];
        *(__half2*)&Ch[(size_t)r0 * Nout + cc] =
            __floats2half2_rn((acc[t][0] + b0) * alpha, (acc[t][1] + b1) * alpha);
        *(__half2*)&Ch[(size_t)r1 * Nout + cc] =
            __floats2half2_rn((acc[t][2] + b0) * alpha, (acc[t][3] + b1) * alpha);
    }
}

// ---------------- fp16 tensor-core fused GEMM (fp32 or fp16 X input) ----------------
// C[M,Nout] = relu?( (X' @ W^T + bias)*alpha + res' )
//   Xh non-null -> fp16 input (ain must be null); else fp32 X with optional ain/bin.
__global__ __launch_bounds__(128) void gemm_h(
    const float* __restrict__ X, const __half* __restrict__ Xh,
    const float* __restrict__ W,
    const float* __restrict__ bias, const float* __restrict__ res,
    const float* __restrict__ ain, const float* __restrict__ bin,
    const float* __restrict__ ra, const float* __restrict__ rb,
    float* __restrict__ C, int M, int K, int Nout, float alpha, int relu)
{
    __shared__ __align__(16) __half x_s[64 * 40];
    __shared__ __align__(16) __half w_s[64 * 40];

    const int tid  = threadIdx.x;
    const int warp = tid >> 5;
    const int lane = tid & 31;
    const int lq = lane >> 2, lr = lane & 3;
    const int n0 = blockIdx.x * 64, m0 = blockIdx.y * 64;
    const int wr = warp * 16;

    float acc[8][4] = {};
    const int ldrow = tid >> 1;
    const int ldc0  = (tid & 1) * 16;

    for (int kt = 0; kt < K; kt += 32) {
        __syncthreads();
        if (Xh) {
            // thread owns 16 halves = 2 x uint4
            uint4 xv0 = *(const uint4*)&Xh[(size_t)(m0 + ldrow) * K + kt + ldc0];
            uint4 xv1 = *(const uint4*)&Xh[(size_t)(m0 + ldrow) * K + kt + ldc0 + 8];
            *(uint4*)&x_s[ldrow * 40 + ldc0]     = xv0;
            *(uint4*)&x_s[ldrow * 40 + ldc0 + 8] = xv1;
            #pragma unroll
            for (int i = 0; i < 4; i++) {
                int c = kt + ldc0 + i * 4;
                float4 wv = *(const float4*)&W[(size_t)(n0 + ldrow) * K + c];
                *(__half2*)&w_s[ldrow * 40 + ldc0 + i * 4]     = __floats2half2_rn(wv.x, wv.y);
                *(__half2*)&w_s[ldrow * 40 + ldc0 + i * 4 + 2] = __floats2half2_rn(wv.z, wv.w);
            }
        } else {
            #pragma unroll
            for (int i = 0; i < 4; i++) {
                int c = kt + ldc0 + i * 4;
                float4 xv = *(const float4*)&X[(size_t)(m0 + ldrow) * K + c];
                if (ain) {
                    xv.x = xv.x * ain[c + 0] + bin[c + 0];
                    xv.y = xv.y * ain[c + 1] + bin[c + 1];
                    xv.z = xv.z * ain[c + 2] + bin[c + 2];
                    xv.w = xv.w * ain[c + 3] + bin[c + 3];
                }
                float4 wv = *(const float4*)&W[(size_t)(n0 + ldrow) * K + c];
                *(__half2*)&x_s[ldrow * 40 + ldc0 + i * 4]     = __floats2half2_rn(xv.x, xv.y);
                *(__half2*)&x_s[ldrow * 40 + ldc0 + i * 4 + 2] = __floats2half2_rn(xv.z, xv.w);
                *(__half2*)&w_s[ldrow * 40 + ldc0 + i * 4]     = __floats2half2_rn(wv.x, wv.y);
                *(__half2*)&w_s[ldrow * 40 + ldc0 + i * 4 + 2] = __floats2half2_rn(wv.z, wv.w);
            }
        }
        __syncthreads();

        unsigned xa[2][4];
        #pragma unroll
        for (int kc = 0; kc < 2; kc++)
            ldm_x4(xa[kc], smem_u32(&x_s[(wr + (lane & 15)) * 40 + kc * 16 + (lane >> 4) * 8]));

        #pragma unroll
        for (int t = 0; t < 8; t++) {
            unsigned kb[4];
            ldm_x4(kb, smem_u32(&w_s[(8 * t + (lane & 7)) * 40 + (lane >> 3) * 8]));
            mma16(acc[t], xa[0], kb[0], kb[1]);
            mma16(acc[t], xa[1], kb[2], kb[3]);
        }
    }

    const int r0 = m0 + wr + lq;
    const int r1 = r0 + 8;
    #pragma unroll
    for (int t = 0; t < 8; t++) {
        #pragma unroll
        for (int j = 0; j < 2; j++) {
            int cc = n0 + t * 8 + 2 * lr + j;
            float b = bias[cc];
            float v0 = (acc[t][j]     + b) * alpha;
            float v1 = (acc[t][2 + j] + b) * alpha;
            if (res) {
                float q0 = res[(size_t)r0 * Nout + cc];
                float q1 = res[(size_t)r1 * Nout + cc];
                if (ra) {
                    float sa = ra[cc], sb = rb[cc];
                    q0 = q0 * sa + sb;
                    q1 = q1 * sa + sb;
                }
                v0 += q0; v1 += q1;
            }
            if (relu) { v0 = fmaxf(v0, 0.f); v1 = fmaxf(v1, 0.f); }
            C[(size_t)r0 * Nout + cc] = v0;
            C[(size_t)r1 * Nout + cc] = v1;
        }
    }
}

// ---------------- fp16 tensor-core flash attention (fp16 I/O) ----------------
// grid (NTOK/64, HEADS), 128 threads = 4 warps, warp owns 16 q-rows.
__global__ __launch_bounds__(128) void flash_attn_h(
    const __half* __restrict__ Q, const __half* __restrict__ Kb,
    const __half* __restrict__ Vb, const float* __restrict__ A,
    __half* __restrict__ O)
{
    __shared__ __align__(16) __half k_s[64 * 40];
    __shared__ __align__(16) __half v_s[64 * 40];

    const int tid  = threadIdx.x;
    const int warp = tid >> 5;
    const int lane = tid & 31;
    const int lq = lane >> 2;      // group 0..7
    const int lr = lane & 3;       // 0..3
    const int h  = blockIdx.y;
    const int q0 = blockIdx.x * 64;
    const int wr = warp * 16;

    const __half* __restrict__ Qh = Q  + (size_t)h * NTOK * HD;
    const __half* __restrict__ Kh = Kb + (size_t)h * NTOK * HD;
    const __half* __restrict__ Vh = Vb + (size_t)h * NTOK * HD;

    const int gr0 = q0 + wr + lq;
    const int gr1 = gr0 + 8;

    // Q A-fragments: direct 4-B loads of packed half2 (no cvt)
    unsigned qa[2][4];
    #pragma unroll
    for (int kc = 0; kc < 2; kc++) {
        int c = kc * 16 + 2 * lr;
        qa[kc][0] = *(const unsigned*)&Qh[(size_t)gr0 * HD + c];
        qa[kc][1] = *(const unsigned*)&Qh[(size_t)gr1 * HD + c];
        qa[kc][2] = *(const unsigned*)&Qh[(size_t)gr0 * HD + c + 8];
        qa[kc][3] = *(const unsigned*)&Qh[(size_t)gr1 * HD + c + 8];
    }

    float m0 = -1e30f, m1 = -1e30f, l0 = 0.f, l1 = 0.f;
    float o[4][4] = {};

    // loaders: thread covers half a K/V row (16 halves = 2 x uint4)
    const int ldrow = tid >> 1;
    const int ldc0  = (tid & 1) * 16;

    for (int kt = 0; kt < NTOK / 64; kt++) {
        const int k0 = kt * 64;

        // adjacency prefetch (gmem, overlaps smem fill)
        float2 am0[8], am1[8];
        #pragma unroll
        for (int t = 0; t < 8; t++) {
            int c = k0 + t * 8 + lr * 2;
            am0[t] = *(const float2*)&A[(size_t)gr0 * NTOK + c];
            am1[t] = *(const float2*)&A[(size_t)gr1 * NTOK + c];
        }

        __syncthreads();
        {
            uint4 kf0 = *(const uint4*)&Kh[(size_t)(k0 + ldrow) * HD + ldc0];
            uint4 kf1 = *(const uint4*)&Kh[(size_t)(k0 + ldrow) * HD + ldc0 + 8];
            uint4 vf0 = *(const uint4*)&Vh[(size_t)(k0 + ldrow) * HD + ldc0];
            uint4 vf1 = *(const uint4*)&Vh[(size_t)(k0 + ldrow) * HD + ldc0 + 8];
            *(uint4*)&k_s[ldrow * 40 + ldc0]     = kf0;
            *(uint4*)&k_s[ldrow * 40 + ldc0 + 8] = kf1;
            *(uint4*)&v_s[ldrow * 40 + ldc0]     = vf0;
            *(uint4*)&v_s[ldrow * 40 + ldc0 + 8] = vf1;
        }
        __syncthreads();

        // ---- QK^T: S(16x64) ----
        float s[8][4] = {};
        #pragma unroll
        for (int t = 0; t < 8; t++) {
            unsigned kb[4];
            unsigned addr = smem_u32(&k_s[(8 * t + (lane & 7)) * 40 + (lane >> 3) * 8]);
            ldm_x4(kb, addr);
            mma16(s[t], qa[0], kb[0], kb[1]);
            mma16(s[t], qa[1], kb[2], kb[3]);
        }

        // ---- mask + online softmax ----
        float mt0 = -1e30f, mt1 = -1e30f;
        #pragma unroll
        for (int t = 0; t < 8; t++) {
            s[t][0] *= am0[t].x; s[t][1] *= am0[t].y;
            s[t][2] *= am1[t].x; s[t][3] *= am1[t].y;
            mt0 = fmaxf(mt0, fmaxf(s[t][0], s[t][1]));
            mt1 = fmaxf(mt1, fmaxf(s[t][2], s[t][3]));
        }
        #pragma unroll
        for (int off = 1; off <= 2; off <<= 1) {
            mt0 = fmaxf(mt0, __shfl_xor_sync(0xffffffffu, mt0, off));
            mt1 = fmaxf(mt1, __shfl_xor_sync(0xffffffffu, mt1, off));
        }
        float mn0 = fmaxf(m0, mt0), mn1 = fmaxf(m1, mt1);
        float cor0 = __expf(m0 - mn0), cor1 = __expf(m1 - mn1);
        l0 *= cor0; l1 *= cor1;
        #pragma unroll
        for (int t = 0; t < 4; t++) {
            o[t][0] *= cor0; o[t][1] *= cor0;
            o[t][2] *= cor1; o[t][3] *= cor1;
        }
        m0 = mn0; m1 = mn1;

        float rs0 = 0.f, rs1 = 0.f;
        #pragma unroll
        for (int t = 0; t < 8; t++) {
            s[t][0] = __expf(s[t][0] - mn0);
            s[t][1] = __expf(s[t][1] - mn0);
            s[t][2] = __expf(s[t][2] - mn1);
            s[t][3] = __expf(s[t][3] - mn1);
            rs0 += s[t][0] + s[t][1];
            rs1 += s[t][2] + s[t][3];
        }
        #pragma unroll
        for (int off = 1; off <= 2; off <<= 1) {
            rs0 += __shfl_xor_sync(0xffffffffu, rs0, off);
            rs1 += __shfl_xor_sync(0xffffffffu, rs1, off);
        }
        l0 += rs0; l1 += rs1;

        // ---- PV: O(16x32) += P(16x64) * V(64x32), P in registers ----
        #pragma unroll
        for (int kc = 0; kc < 4; kc++) {
            unsigned pa[4];
            pa[0] = packh2(s[2 * kc][0],     s[2 * kc][1]);
            pa[1] = packh2(s[2 * kc][2],     s[2 * kc][3]);
            pa[2] = packh2(s[2 * kc + 1][0], s[2 * kc + 1][1]);
            pa[3] = packh2(s[2 * kc + 1][2], s[2 * kc + 1][3]);
            #pragma unroll
            for (int tp = 0; tp < 2; tp++) {
                unsigned vb[4];
                int key = 16 * kc + ((lane >> 3) & 1) * 8 + (lane & 7);
                int dof = 16 * tp + (lane >> 4) * 8;
                unsigned addr = smem_u32(&v_s[key * 40 + dof]);
                ldm_x4_t(vb, addr);
                mma16(o[2 * tp],     pa, vb[0], vb[1]);
                mma16(o[2 * tp + 1], pa, vb[2], vb[3]);
            }
        }
    }

    // ---- epilogue: fp16 output ----
    float inv0 = 1.f / l0, inv1 = 1.f / l1;
    __half* __restrict__ Oh = O + (size_t)h * NTOK * HD;
    #pragma unroll
    for (int t = 0; t < 4; t++) {
        int c = t * 8 + lr * 2;
        *(__half2*)&Oh[(size_t)gr0 * HD + c] = __floats2half2_rn(o[t][0] * inv0, o[t][1] * inv0);
        *(__half2*)&Oh[(size_t)gr1 * HD + c] = __floats2half2_rn(o[t][2] * inv1, o[t][3] * inv1);
    }
}

// ---------------- batchnorm column stats -> fused scale/shift ----------------
__global__ __launch_bounds__(128) void colstats(
    const float* __restrict__ Y, const float* __restrict__ g,
    const float* __restrict__ be, float* __restrict__ a, float* __restrict__ b)
{
    const int c = blockIdx.x;
    const int t = threadIdx.x;
    float s = 0.f, sq = 0.f;
    for (int r = t; r < NTOK; r += 128) {
        float v = Y[(size_t)r * HID + c];
        s += v; sq += v * v;
    }
    __shared__ float ss[128], qq[128];
    ss[t] = s; qq[t] = sq;
    __syncthreads();
    for (int off = 64; off; off >>= 1) {
        if (t < off) { ss[t] += ss[t + off]; qq[t] += qq[t + off]; }
        __syncthreads();
    }
    if (t == 0) {
        float mean = ss[0] * (1.f / NTOK);
        float var  = qq[0] * (1.f / NTOK) - mean * mean;
        float sc = g[c] * rsqrtf(var + EPSV);
        a[c] = sc;
        b[c] = be[c] - mean * sc;
    }
}

// ---------------- final affine to output ----------------
__global__ __launch_bounds__(256) void affine_out(
    const float* __restrict__ Y, const float* __restrict__ a,
    const float* __restrict__ b, float* __restrict__ out)
{
    int i = blockIdx.x * 256 + threadIdx.x;
    int c = i & (HID - 1);
    out[i] = Y[i] * a[c] + b[c];
}

// ---------------- launch ----------------
extern "C" void kernel_launch(void* const* d_in, const int* in_sizes, int n_in,
                              void* d_out, int out_size)
{
    const float* A  = (const float*)d_in[0];
    const float* h  = (const float*)d_in[1];
    const float* Wq = (const float*)d_in[2];
    const float* bq = (const float*)d_in[3];
    const float* Wk = (const float*)d_in[4];
    const float* bk = (const float*)d_in[5];
    const float* Wv = (const float*)d_in[6];
    const float* bv = (const float*)d_in[7];
    const float* Wo = (const float*)d_in[8];
    const float* bo = (const float*)d_in[9];
    const float* W1 = (const float*)d_in[10];
    const float* c1 = (const float*)d_in[11];
    const float* W2 = (const float*)d_in[12];
    const float* c2 = (const float*)d_in[13];
    const float* g1 = (const float*)d_in[14];
    const float* be1 = (const float*)d_in[15];
    const float* g2 = (const float*)d_in[16];
    const float* be2 = (const float*)d_in[17];
    float* out = (float*)d_out;

    __half *Qp, *Kp, *Vp, *Op;
    float *y1p, *zp, *y2p, *a1p, *b1p, *a2p, *b2p;
    cudaGetSymbolAddress((void**)&Qp,  g_Qh);
    cudaGetSymbolAddress((void**)&Kp,  g_Kh);
    cudaGetSymbolAddress((void**)&Vp,  g_Vh);
    cudaGetSymbolAddress((void**)&Op,  g_Oh);
    cudaGetSymbolAddress((void**)&y1p, g_y1);
    cudaGetSymbolAddress((void**)&zp,  g_z);
    cudaGetSymbolAddress((void**)&y2p, g_y2);
    cudaGetSymbolAddress((void**)&a1p, g_a1);
    cudaGetSymbolAddress((void**)&b1p, g_b1);
    cudaGetSymbolAddress((void**)&a2p, g_a2);
    cudaGetSymbolAddress((void**)&b2p, g_b2);

    const float scaling = 0.17677669529663687f;  // HD^-0.5

    dim3 grid_qkv(HID / 64, NTOK / 64, 3);
    dim3 grid_g(HID / 64, NTOK / 64);

    // Q/K/V projections fused in one launch, fp16 outputs
    gemm_qkv<<<grid_qkv, 128>>>(h, Wq, bq, Wk, bk, Wv, bv, Qp, Kp, Vp, scaling);

    flash_attn_h<<<dim3(NTOK / 64, HEADS), 128>>>(Qp, Kp, Vp, A, Op);

    // y1 = attn @ Wo^T + bo + h   (fp16 X input)
    gemm_h<<<grid_g, 128>>>(nullptr, Op, Wo, bo, h, nullptr, nullptr, nullptr, nullptr,
                            y1p, NTOK, HID, HID, 1.f, 0);

    colstats<<<HID, 128>>>(y1p, g1, be1, a1p, b1p);

    // z = relu( bn1(y1) @ W1^T + c1 )   [N, 512]
    gemm_h<<<dim3(2 * HID / 64, NTOK / 64), 128>>>(
        y1p, nullptr, W1, c1, nullptr, a1p, b1p, nullptr, nullptr,
        zp, NTOK, HID, 2 * HID, 1.f, 1);

    // y2 = z @ W2^T + c2 + bn1(y1)
    gemm_h<<<grid_g, 128>>>(zp, nullptr, W2, c2, y1p, nullptr, nullptr, a1p, b1p,
                            y2p, NTOK, 2 * HID, HID, 1.f, 0);

    colstats<<<HID, 128>>>(y2p, g2, be2, a2p, b2p);

    affine_out<<<NTOK * HID / 256, 256>>>(y2p, a2p, b2p, out);
}